// round 6
// baseline (speedup 1.0000x reference)
#include <cuda_runtime.h>
#include <cstdint>

// QuantumLinear == x @ W_real^T + bias  (magnitude*cos(atan2(i,r)) == r identically;
// weight_imag is dead code).
//
// Round 6: tf32 mma.m16n8k8, pre-rounded inputs. Warp tile 64x64 (32 MMA / 8 ldsm
// = 128B smem per MMA, was 192B) to relieve the smem crossbar co-limiter.
// CTA 128x256, 8 warps (2m x 4n), 1 CTA/SM, 4-stage cp.async pipeline (216KB smem).

#define M_DIM 8192
#define N_DIM 4096
#define K_DIM 4096

#define BM 128
#define BN 256
#define BK 32                       // fp32 elements per K-tile (128B rows)
#define STAGES 4
#define KTILES (K_DIM / BK)         // 128

// smem rows padded: 128B data + 16B pad = 144B (odd multiple of 16 -> conflict-free)
#define ROW_STRIDE 144
#define A_TILE_BYTES (BM * ROW_STRIDE)          // 18432
#define B_TILE_BYTES (BN * ROW_STRIDE)          // 36864
#define STAGE_BYTES  (A_TILE_BYTES + B_TILE_BYTES)  // 55296
#define SMEM_TOTAL   (STAGES * STAGE_BYTES)     // 221184 (216KB)

// ---------------- scratch: tf32-rounded copies ----------------
__device__ float g_xr[(size_t)M_DIM * K_DIM];
__device__ float g_wr[(size_t)N_DIM * K_DIM];

// ---------------- helpers ----------------
__device__ __forceinline__ uint32_t smem_u32(const void* p) {
    uint32_t a;
    asm("{ .reg .u64 t; cvta.to.shared.u64 t, %1; cvt.u32.u64 %0, t; }" : "=r"(a) : "l"(p));
    return a;
}

__device__ __forceinline__ void cp16(uint32_t dst, const void* src) {
    asm volatile("cp.async.cg.shared.global [%0], [%1], 16;" :: "r"(dst), "l"(src));
}
#define CP_COMMIT() asm volatile("cp.async.commit_group;" ::: "memory")
#define CP_WAIT(n)  asm volatile("cp.async.wait_group %0;" :: "n"(n) : "memory")

__device__ __forceinline__ void ldsm4(uint32_t* r, uint32_t addr) {
    asm volatile("ldmatrix.sync.aligned.m8n8.x4.shared.b16 {%0,%1,%2,%3}, [%4];"
                 : "=r"(r[0]), "=r"(r[1]), "=r"(r[2]), "=r"(r[3]) : "r"(addr));
}

__device__ __forceinline__ void mma1688(float* d, const uint32_t* a,
                                        uint32_t b0, uint32_t b1) {
    asm volatile(
        "mma.sync.aligned.m16n8k8.row.col.f32.tf32.tf32.f32 "
        "{%0,%1,%2,%3}, {%4,%5,%6,%7}, {%8,%9}, {%0,%1,%2,%3};"
        : "+f"(d[0]), "+f"(d[1]), "+f"(d[2]), "+f"(d[3])
        : "r"(a[0]), "r"(a[1]), "r"(a[2]), "r"(a[3]), "r"(b0), "r"(b1));
}

// ---------------- prep: fp32 -> tf32-exact fp32 (round-to-nearest) ----------------
__global__ __launch_bounds__(256)
void round_tf32(const uint4* __restrict__ src, uint4* __restrict__ dst, int n4)
{
    int i = blockIdx.x * blockDim.x + threadIdx.x;
    if (i >= n4) return;
    uint4 v = src[i];
    asm("cvt.rna.tf32.f32 %0, %0;" : "+r"(v.x));
    asm("cvt.rna.tf32.f32 %0, %0;" : "+r"(v.y));
    asm("cvt.rna.tf32.f32 %0, %0;" : "+r"(v.z));
    asm("cvt.rna.tf32.f32 %0, %0;" : "+r"(v.w));
    dst[i] = v;
}

// ---------------- GEMM ----------------
__global__ __launch_bounds__(256, 1)
void qgemm_tf32(const float* __restrict__ X,    // [M, K] tf32-exact
                const float* __restrict__ W,    // [N, K] tf32-exact
                const float* __restrict__ bias, // [N]
                float* __restrict__ out)        // [M, N]
{
    extern __shared__ char smem[];
    const uint32_t sb = smem_u32(smem);

    const int tid  = threadIdx.x;
    const int wid  = tid >> 5;
    const int lane = tid & 31;
    const int warpM = wid & 1;      // m offset 64*warpM
    const int warpN = wid >> 1;     // n offset 64*warpN (0..3)

    // ---- grouped rasterization: 8 m-tiles per group column ----
    // grid = 64 (m) x 16 (n) = 1024; group = 8m x 16n = 128 blocks
    const int pid = blockIdx.x;
    const int group_id = pid >> 7;
    const int pid_m = (group_id << 3) + (pid & 7);
    const int pid_n = (pid & 127) >> 3;
    const int bm = pid_m * BM;
    const int bn = pid_n * BN;

    // ---- global load mapping ----
    const int r = tid >> 1;          // 0..127
    const int h = tid & 1;           // 64B half of 128B row
    const size_t aOff  = (size_t)(bm + r) * K_DIM + h * 16;
    const size_t bOff0 = (size_t)(bn + r) * K_DIM + h * 16;
    const size_t bOff1 = bOff0 + (size_t)128 * K_DIM;
    const uint32_t sRowA  = (uint32_t)(r * ROW_STRIDE + h * 64);
    const uint32_t sRowB0 = (uint32_t)(A_TILE_BYTES + r * ROW_STRIDE + h * 64);
    const uint32_t sRowB1 = sRowB0 + 128 * ROW_STRIDE;

    // ---- ldmatrix lane bases ----
    const uint32_t aLane = sb +
        (uint32_t)((warpM * 64 + (lane & 15)) * ROW_STRIDE + ((lane >> 4) * 16));
    const uint32_t bLane = sb + A_TILE_BYTES +
        (uint32_t)((warpN * 64 + (lane & 7) + ((lane & 16) >> 1)) * ROW_STRIDE +
                   (((lane >> 3) & 1) * 16));

    float acc[4][8][4];
    #pragma unroll
    for (int i = 0; i < 4; i++)
        #pragma unroll
        for (int j = 0; j < 8; j++)
            #pragma unroll
            for (int q = 0; q < 4; q++)
                acc[i][j][q] = 0.0f;

    // ---- prologue: issue stages 0..STAGES-2 ----
    #pragma unroll
    for (int s = 0; s < STAGES - 1; s++) {
        const int k0 = s * BK;
        const uint32_t st = sb + s * STAGE_BYTES;
        #pragma unroll
        for (int c = 0; c < 4; c++) {
            cp16(st + sRowA  + c * 16, X + aOff  + k0 + c * 4);
            cp16(st + sRowB0 + c * 16, W + bOff0 + k0 + c * 4);
            cp16(st + sRowB1 + c * 16, W + bOff1 + k0 + c * 4);
        }
        CP_COMMIT();
    }

    uint32_t bufC = 0;
    uint32_t bufL = (STAGES - 1) * STAGE_BYTES;

    // double-buffered fragments
    uint32_t ar[2][4][4];   // [buf][mt][reg]
    uint32_t br[2][4][4];   // [buf][npair][reg]

    // ---- main loop ----
    #pragma unroll 1
    for (int s = 0; s < KTILES; s++) {
        CP_WAIT(STAGES - 2);
        __syncthreads();

        const int ls = s + STAGES - 1;
        if (ls < KTILES) {
            const int k0 = ls * BK;
            const uint32_t st = sb + bufL;
            #pragma unroll
            for (int c = 0; c < 4; c++) {
                cp16(st + sRowA  + c * 16, X + aOff  + k0 + c * 4);
                cp16(st + sRowB0 + c * 16, W + bOff0 + k0 + c * 4);
                cp16(st + sRowB1 + c * 16, W + bOff1 + k0 + c * 4);
            }
        }
        CP_COMMIT();

        // fragments for slice 0
        #pragma unroll
        for (int mt = 0; mt < 4; mt++)
            ldsm4(ar[0][mt], aLane + bufC + mt * (16 * ROW_STRIDE));
        #pragma unroll
        for (int p = 0; p < 4; p++)
            ldsm4(br[0][p], bLane + bufC + p * (16 * ROW_STRIDE));

        #pragma unroll
        for (int ks = 0; ks < 4; ks++) {
            const int cur = ks & 1;
            const int nxt = cur ^ 1;
            if (ks < 3) {   // prefetch slice ks+1 while computing ks
                const uint32_t o = bufC + (ks + 1) * 32;
                #pragma unroll
                for (int mt = 0; mt < 4; mt++)
                    ldsm4(ar[nxt][mt], aLane + o + mt * (16 * ROW_STRIDE));
                #pragma unroll
                for (int p = 0; p < 4; p++)
                    ldsm4(br[nxt][p], bLane + o + p * (16 * ROW_STRIDE));
            }
            #pragma unroll
            for (int mt = 0; mt < 4; mt++)
                #pragma unroll
                for (int nt = 0; nt < 8; nt++)
                    mma1688(acc[mt][nt], ar[cur][mt],
                            br[cur][nt >> 1][(nt & 1) * 2],
                            br[cur][nt >> 1][(nt & 1) * 2 + 1]);
        }

        bufC += STAGE_BYTES; if (bufC == SMEM_TOTAL) bufC = 0;
        bufL += STAGE_BYTES; if (bufL == SMEM_TOTAL) bufL = 0;
    }

    // ---- epilogue: direct stores + bias ----
    const int g = lane >> 2;
    const int t = lane & 3;
    #pragma unroll
    for (int mt = 0; mt < 4; mt++) {
        const int row0 = bm + warpM * 64 + mt * 16 + g;
        #pragma unroll
        for (int nt = 0; nt < 8; nt++) {
            const int col = bn + warpN * 64 + nt * 8 + 2 * t;
            const float2 b2 = *(const float2*)(bias + col);
            float2 o0, o1;
            o0.x = acc[mt][nt][0] + b2.x;
            o0.y = acc[mt][nt][1] + b2.y;
            o1.x = acc[mt][nt][2] + b2.x;
            o1.y = acc[mt][nt][3] + b2.y;
            *(float2*)(out + (size_t)row0 * N_DIM + col)       = o0;
            *(float2*)(out + (size_t)(row0 + 8) * N_DIM + col) = o1;
        }
    }
}

// ---------------- host ----------------
extern "C" void kernel_launch(void* const* d_in, const int* in_sizes, int n_in,
                              void* d_out, int out_size)
{
    const float* x    = (const float*)d_in[0];   // [M, K]
    const float* wr   = (const float*)d_in[1];   // [N, K]
    // d_in[2] = weight_imag: algebraically dead
    const float* bias = (const float*)d_in[3];   // [N]
    float* out = (float*)d_out;

    void *p_xr, *p_wr;
    cudaGetSymbolAddress(&p_xr, g_xr);
    cudaGetSymbolAddress(&p_wr, g_wr);

    {
        int n4x = M_DIM * K_DIM / 4;
        int n4w = N_DIM * K_DIM / 4;
        round_tf32<<<n4x / 256, 256>>>((const uint4*)x, (uint4*)p_xr, n4x);
        round_tf32<<<n4w / 256, 256>>>((const uint4*)wr, (uint4*)p_wr, n4w);
    }

    cudaFuncSetAttribute(qgemm_tf32, cudaFuncAttributeMaxDynamicSharedMemorySize,
                         SMEM_TOTAL);

    const int nblocks = (M_DIM / BM) * (N_DIM / BN);   // 1024
    qgemm_tf32<<<nblocks, 256, SMEM_TOTAL>>>(
        (const float*)p_xr, (const float*)p_wr, bias, out);
}

// round 7
// speedup vs baseline: 2.4911x; 2.4911x over previous
#include <cuda_runtime.h>
#include <cuda_fp16.h>
#include <cstdint>

// QuantumLinear == x @ W_real^T + bias  (magnitude*cos(atan2(i,r)) == r identically;
// weight_imag is dead code).
//
// Round 7: fallback HMMA is paced PER INSTRUCTION (~15 cyc/SMSP regardless of
// MMA shape; R3/R5 evidence). So use the largest base-ISA MMA: m16n8k16 fp16
// (4096 FLOP/instr) SINGLE PASS -> 67M instrs (tf32 k8 needed 134M).
// fp16 mantissa (10 bits) == tf32 mantissa -> same rel_err ~3e-4 as R5.
// Inputs pre-converted fp32 -> fp16 (rn) in a prep pass.

#define M_DIM 8192
#define N_DIM 4096
#define K_DIM 4096

#define BM 128
#define BN 128
#define BK 32                       // fp16 elements per K-tile (64B rows)
#define STAGES 4
#define KTILES (K_DIM / BK)         // 128

// smem rows: 64B data + 16B pad = 80B stride -> conflict-free ldmatrix
#define ROW_STRIDE 80
#define TILE_BYTES (128 * ROW_STRIDE)          // 10240
#define STAGE_BYTES (2 * TILE_BYTES)           // 20480
#define SMEM_TOTAL (STAGES * STAGE_BYTES)      // 81920

// ---------------- scratch: fp16 copies ----------------
__device__ __half g_xh[(size_t)M_DIM * K_DIM];
__device__ __half g_wh[(size_t)N_DIM * K_DIM];

// ---------------- helpers ----------------
__device__ __forceinline__ uint32_t smem_u32(const void* p) {
    uint32_t a;
    asm("{ .reg .u64 t; cvta.to.shared.u64 t, %1; cvt.u32.u64 %0, t; }" : "=r"(a) : "l"(p));
    return a;
}

__device__ __forceinline__ void cp16(uint32_t dst, const void* src) {
    asm volatile("cp.async.cg.shared.global [%0], [%1], 16;" :: "r"(dst), "l"(src));
}
#define CP_COMMIT() asm volatile("cp.async.commit_group;" ::: "memory")
#define CP_WAIT(n)  asm volatile("cp.async.wait_group %0;" :: "n"(n) : "memory")

__device__ __forceinline__ void ldsm4(uint32_t* r, uint32_t addr) {
    asm volatile("ldmatrix.sync.aligned.m8n8.x4.shared.b16 {%0,%1,%2,%3}, [%4];"
                 : "=r"(r[0]), "=r"(r[1]), "=r"(r[2]), "=r"(r[3]) : "r"(addr));
}

__device__ __forceinline__ void mma16816(float* d, const uint32_t* a,
                                         uint32_t b0, uint32_t b1) {
    asm volatile(
        "mma.sync.aligned.m16n8k16.row.col.f32.f16.f16.f32 "
        "{%0,%1,%2,%3}, {%4,%5,%6,%7}, {%8,%9}, {%0,%1,%2,%3};"
        : "+f"(d[0]), "+f"(d[1]), "+f"(d[2]), "+f"(d[3])
        : "r"(a[0]), "r"(a[1]), "r"(a[2]), "r"(a[3]), "r"(b0), "r"(b1));
}

// ---------------- prep: fp32 -> fp16 (rn) ----------------
__global__ __launch_bounds__(256)
void to_fp16(const float4* __restrict__ src, __half2* __restrict__ dst, int n4)
{
    int i = blockIdx.x * blockDim.x + threadIdx.x;
    if (i >= n4) return;
    float4 v = src[i];
    dst[2 * i]     = __floats2half2_rn(v.x, v.y);
    dst[2 * i + 1] = __floats2half2_rn(v.z, v.w);
}

// ---------------- GEMM ----------------
__global__ __launch_bounds__(256, 2)
void qgemm_fp16(const __half* __restrict__ X,   // [M, K] fp16
                const __half* __restrict__ W,   // [N, K] fp16
                const float* __restrict__ bias, // [N]
                float* __restrict__ out)        // [M, N]
{
    extern __shared__ char smem[];
    const uint32_t sb = smem_u32(smem);

    const int tid  = threadIdx.x;
    const int wid  = tid >> 5;
    const int lane = tid & 31;
    const int warpM = wid & 3;      // m offset 32*warpM
    const int warpN = wid >> 2;     // n offset 64*warpN

    // ---- grouped rasterization: 8 m-tiles per group column ----
    const int pid = blockIdx.x;
    const int group_id = pid >> 8;
    const int pid_m = (group_id << 3) + (pid & 7);
    const int pid_n = (pid & 255) >> 3;
    const int bm = pid_m * BM;
    const int bn = pid_n * BN;

    // ---- global load mapping: 2 rows per thread per tile, 16B chunks ----
    const int ldr   = tid >> 2;       // 0..63
    const int chunk = tid & 3;        // 0..3 (16B = 8 halves)
    const size_t aOff0 = (size_t)(bm + ldr) * K_DIM + chunk * 8;
    const size_t aOff1 = aOff0 + (size_t)64 * K_DIM;
    const size_t bOff0 = (size_t)(bn + ldr) * K_DIM + chunk * 8;
    const size_t bOff1 = bOff0 + (size_t)64 * K_DIM;
    const uint32_t sA0 = ldr * ROW_STRIDE + chunk * 16;
    const uint32_t sA1 = sA0 + 64 * ROW_STRIDE;

    // ---- ldmatrix lane bases ----
    const uint32_t aLane = sb +
        (uint32_t)((warpM * 32 + (lane & 15)) * ROW_STRIDE + ((lane >> 4) * 16));
    const uint32_t bLane = sb + TILE_BYTES +
        (uint32_t)((warpN * 64 + (lane & 7) + ((lane & 16) >> 1)) * ROW_STRIDE +
                   (((lane >> 3) & 1) * 16));

    float acc[2][8][4];
    #pragma unroll
    for (int i = 0; i < 2; i++)
        #pragma unroll
        for (int j = 0; j < 8; j++)
            #pragma unroll
            for (int q = 0; q < 4; q++)
                acc[i][j][q] = 0.0f;

    // ---- prologue: issue stages 0..STAGES-2 ----
    #pragma unroll
    for (int s = 0; s < STAGES - 1; s++) {
        const int k0 = s * BK;
        const uint32_t st = sb + s * STAGE_BYTES;
        cp16(st + sA0, X + aOff0 + k0);
        cp16(st + sA1, X + aOff1 + k0);
        cp16(st + TILE_BYTES + sA0, W + bOff0 + k0);
        cp16(st + TILE_BYTES + sA1, W + bOff1 + k0);
        CP_COMMIT();
    }

    uint32_t bufC = 0;
    uint32_t bufL = (STAGES - 1) * STAGE_BYTES;

    // double-buffered fragments
    uint32_t ar[2][2][4];   // [buf][mt][reg]
    uint32_t br[2][4][4];   // [buf][npair][reg]

    // ---- main loop ----
    #pragma unroll 1
    for (int s = 0; s < KTILES; s++) {
        CP_WAIT(STAGES - 2);
        __syncthreads();

        const int ls = s + STAGES - 1;
        if (ls < KTILES) {
            const int k0 = ls * BK;
            const uint32_t st = sb + bufL;
            cp16(st + sA0, X + aOff0 + k0);
            cp16(st + sA1, X + aOff1 + k0);
            cp16(st + TILE_BYTES + sA0, W + bOff0 + k0);
            cp16(st + TILE_BYTES + sA1, W + bOff1 + k0);
        }
        CP_COMMIT();

        // fragments for k-slice 0
        ldsm4(ar[0][0], aLane + bufC);
        ldsm4(ar[0][1], aLane + bufC + 16 * ROW_STRIDE);
        #pragma unroll
        for (int p = 0; p < 4; p++)
            ldsm4(br[0][p], bLane + bufC + p * (16 * ROW_STRIDE));

        #pragma unroll
        for (int ks = 0; ks < 2; ks++) {
            const int cur = ks & 1;
            const int nxt = cur ^ 1;
            if (ks < 1) {   // prefetch slice 1 while computing slice 0
                const uint32_t o = bufC + 32;
                ldsm4(ar[nxt][0], aLane + o);
                ldsm4(ar[nxt][1], aLane + o + 16 * ROW_STRIDE);
                #pragma unroll
                for (int p = 0; p < 4; p++)
                    ldsm4(br[nxt][p], bLane + o + p * (16 * ROW_STRIDE));
            }
            #pragma unroll
            for (int mt = 0; mt < 2; mt++)
                #pragma unroll
                for (int nt = 0; nt < 8; nt++)
                    mma16816(acc[mt][nt], ar[cur][mt],
                             br[cur][nt >> 1][(nt & 1) * 2],
                             br[cur][nt >> 1][(nt & 1) * 2 + 1]);
        }

        bufC += STAGE_BYTES; if (bufC == SMEM_TOTAL) bufC = 0;
        bufL += STAGE_BYTES; if (bufL == SMEM_TOTAL) bufL = 0;
    }

    // ---- epilogue: direct stores + bias ----
    const int g = lane >> 2;
    const int t = lane & 3;
    #pragma unroll
    for (int mt = 0; mt < 2; mt++) {
        const int row0 = bm + warpM * 32 + mt * 16 + g;
        #pragma unroll
        for (int nt = 0; nt < 8; nt++) {
            const int col = bn + warpN * 64 + nt * 8 + 2 * t;
            const float2 b2 = *(const float2*)(bias + col);
            float2 o0, o1;
            o0.x = acc[mt][nt][0] + b2.x;
            o0.y = acc[mt][nt][1] + b2.y;
            o1.x = acc[mt][nt][2] + b2.x;
            o1.y = acc[mt][nt][3] + b2.y;
            *(float2*)(out + (size_t)row0 * N_DIM + col)       = o0;
            *(float2*)(out + (size_t)(row0 + 8) * N_DIM + col) = o1;
        }
    }
}

// ---------------- host ----------------
extern "C" void kernel_launch(void* const* d_in, const int* in_sizes, int n_in,
                              void* d_out, int out_size)
{
    const float* x    = (const float*)d_in[0];   // [M, K]
    const float* wr   = (const float*)d_in[1];   // [N, K]
    // d_in[2] = weight_imag: algebraically dead
    const float* bias = (const float*)d_in[3];   // [N]
    float* out = (float*)d_out;

    void *p_xh, *p_wh;
    cudaGetSymbolAddress(&p_xh, g_xh);
    cudaGetSymbolAddress(&p_wh, g_wh);

    {
        int n4x = M_DIM * K_DIM / 4;
        int n4w = N_DIM * K_DIM / 4;
        to_fp16<<<n4x / 256, 256>>>((const float4*)x, (__half2*)p_xh, n4x);
        to_fp16<<<n4w / 256, 256>>>((const float4*)wr, (__half2*)p_wh, n4w);
    }

    cudaFuncSetAttribute(qgemm_fp16, cudaFuncAttributeMaxDynamicSharedMemorySize,
                         SMEM_TOTAL);

    const int nblocks = (M_DIM / BM) * (N_DIM / BN);   // 2048
    qgemm_fp16<<<nblocks, 256, SMEM_TOTAL>>>(
        (const __half*)p_xh, (const __half*)p_wh, bias, out);
}